// round 3
// baseline (speedup 1.0000x reference)
#include <cuda_runtime.h>

#define NN 50000
#define EE 800000
#define NEG 0.2f

// ---------------- scratch (device globals; 16B-aligned for v4 access) -------
__device__ __align__(16) int   g_src[EE];
__device__ __align__(16) int   g_dst[EE];
__device__ __align__(16) float g_e[EE * 4];
__device__ __align__(16) float g_h[NN * 64];
__device__ __align__(16) float g_featA[NN * 64];
__device__ __align__(16) float g_featB[NN * 64];
__device__ __align__(16) float g_accum[NN * 64];
__device__ __align__(16) float g_as[NN * 4];
__device__ __align__(16) float g_ad[NN * 4];
__device__ __align__(16) float g_m[NN * 4];
__device__ __align__(16) float g_den[NN * 4];
__device__ int g_is64;

// ---------------- helpers ---------------------------------------------------
__device__ __forceinline__ float atomicMaxF(float* a, float v) {
    if (v >= 0.f)
        return __int_as_float(atomicMax((int*)a, __float_as_int(v)));
    return __uint_as_float(atomicMin((unsigned int*)a, __float_as_uint(v)));
}

__device__ __forceinline__ void redAddV4(float* a, float4 v) {
    asm volatile("red.global.add.v4.f32 [%0], {%1,%2,%3,%4};"
                 :: "l"(a), "f"(v.x), "f"(v.y), "f"(v.z), "f"(v.w)
                 : "memory");
}

__device__ __forceinline__ float lrelu(float x) { return x > 0.f ? x : NEG * x; }

// ---------------- kernels ---------------------------------------------------
// If edge_index is int64 (values < 2^31), every odd 32-bit word of the first
// 64 lanes is zero. For int32, those words are random node ids.
__global__ void detect_kernel(const int* __restrict__ ei) {
    if (threadIdx.x == 0) {
        int acc = 0;
        for (int i = 1; i < 128; i += 2) acc |= ei[i];
        g_is64 = (acc == 0) ? 1 : 0;
    }
}

__global__ void convert_idx_kernel(const int* __restrict__ ei) {
    int e = blockIdx.x * blockDim.x + threadIdx.x;
    if (e >= EE) return;
    if (g_is64) {
        g_src[e] = ei[2 * e];
        g_dst[e] = ei[2 * (EE + e)];
    } else {
        g_src[e] = ei[e];
        g_dst[e] = ei[EE + e];
    }
}

// h = X @ W  (X:[NN,FIN], W:[FIN,64]) ; also alpha_s/alpha_d, self-loop max init,
// zero denom / accum.  blockDim = (64, 8).
template <int FIN, int H>
__global__ void gemm_alpha_kernel(const float* __restrict__ X,
                                  const float* __restrict__ W,
                                  const float* __restrict__ As,
                                  const float* __restrict__ Ad) {
    const int NB = 8;
    __shared__ float sW[FIN][64];
    __shared__ float sX[NB][FIN];
    __shared__ float sH[NB][65];

    int col = threadIdx.x;
    int ny  = threadIdx.y;
    int tid = ny * 64 + col;
    int node0 = blockIdx.x * NB;

    for (int i = tid; i < FIN * 64; i += 64 * NB) sW[i >> 6][i & 63] = W[i];
    for (int i = tid; i < NB * FIN; i += 64 * NB) sX[i / FIN][i % FIN] = X[node0 * FIN + i];
    __syncthreads();

    float acc = 0.f;
#pragma unroll
    for (int k = 0; k < FIN; k++) acc += sX[ny][k] * sW[k][col];

    int node = node0 + ny;
    if (node < NN) {
        g_h[node * 64 + col]     = acc;
        g_accum[node * 64 + col] = 0.f;
    }
    sH[ny][col] = acc;
    __syncthreads();

    if (col < H && node < NN) {
        const int F = 64 / H;
        float s = 0.f, d = 0.f;
#pragma unroll
        for (int f = 0; f < F; f++) {
            float hv = sH[ny][col * F + f];
            s += hv * As[col * F + f];
            d += hv * Ad[col * F + f];
        }
        g_as[node * H + col] = s;
        g_ad[node * H + col] = d;
        g_m[node * H + col]  = lrelu(s + d);   // self-loop seeds the max
        g_den[node * H + col] = 0.f;
    }
}

template <int H>
__global__ void edge_max_kernel() {
    int e = blockIdx.x * blockDim.x + threadIdx.x;
    if (e >= EE) return;
    int s = g_src[e], d = g_dst[e];
    if (H == 4) {
        float4 a = *(const float4*)&g_as[s * 4];
        float4 b = *(const float4*)&g_ad[d * 4];
        float4 ev;
        ev.x = lrelu(a.x + b.x);
        ev.y = lrelu(a.y + b.y);
        ev.z = lrelu(a.z + b.z);
        ev.w = lrelu(a.w + b.w);
        *(float4*)&g_e[e * 4] = ev;
        atomicMaxF(&g_m[d * 4 + 0], ev.x);
        atomicMaxF(&g_m[d * 4 + 1], ev.y);
        atomicMaxF(&g_m[d * 4 + 2], ev.z);
        atomicMaxF(&g_m[d * 4 + 3], ev.w);
    } else {
        float ev = lrelu(g_as[s] + g_ad[d]);
        g_e[e] = ev;
        atomicMaxF(&g_m[d], ev);
    }
}

// 16 threads per edge; each handles 4 contiguous feature columns.
template <int H>
__global__ void edge_accum_kernel() {
    int idx = blockIdx.x * blockDim.x + threadIdx.x;
    int e = idx >> 4;
    int j = idx & 15;
    if (e >= EE) return;
    int s = g_src[e], d = g_dst[e];
    int head = (H == 4) ? (j >> 2) : 0;
    float ev = g_e[e * H + head];
    float mm = g_m[d * H + head];
    float w  = __expf(ev - mm);

    float4 hv = *(const float4*)&g_h[s * 64 + j * 4];
    redAddV4(&g_accum[d * 64 + j * 4],
             make_float4(hv.x * w, hv.y * w, hv.z * w, hv.w * w));

    if (j == 0) {
        if (H == 4) {
            float4 evv = *(const float4*)&g_e[e * 4];
            float4 mv  = *(const float4*)&g_m[d * 4];
            redAddV4(&g_den[d * 4],
                     make_float4(__expf(evv.x - mv.x), __expf(evv.y - mv.y),
                                 __expf(evv.z - mv.z), __expf(evv.w - mv.w)));
        } else {
            atomicAdd(&g_den[d], w);
        }
    }
}

template <int H, bool ELU>
__global__ void finalize_kernel(const float* __restrict__ bias,
                                float* __restrict__ out) {
    int idx = blockIdx.x * blockDim.x + threadIdx.x;
    if (idx >= NN * 64) return;
    int node = idx >> 6;
    int col  = idx & 63;
    int head = (H == 4) ? (col >> 4) : 0;
    // self-loop contribution (excluded from atomic passes)
    float ev = lrelu(g_as[node * H + head] + g_ad[node * H + head]);
    float w  = __expf(ev - g_m[node * H + head]);
    float num = g_accum[idx] + w * g_h[idx];
    float den = g_den[node * H + head] + w + 1e-16f;
    float v = num / den + bias[col];
    if (ELU) v = v > 0.f ? v : expm1f(v);
    out[idx] = v;
}

// ---------------- launch -----------------------------------------------------
extern "C" void kernel_launch(void* const* d_in, const int* in_sizes, int n_in,
                              void* d_out, int out_size) {
    const float* x   = (const float*)d_in[0];
    const int*   ei  = (const int*)d_in[1];
    const float* W0  = (const float*)d_in[2];
    const float* as0 = (const float*)d_in[3];
    const float* ad0 = (const float*)d_in[4];
    const float* b0  = (const float*)d_in[5];
    const float* W1  = (const float*)d_in[6];
    const float* as1 = (const float*)d_in[7];
    const float* ad1 = (const float*)d_in[8];
    const float* b1  = (const float*)d_in[9];
    const float* W2  = (const float*)d_in[10];
    const float* as2 = (const float*)d_in[11];
    const float* ad2 = (const float*)d_in[12];
    const float* b2  = (const float*)d_in[13];
    float* out = (float*)d_out;

    float *featA, *featB;
    cudaGetSymbolAddress((void**)&featA, g_featA);
    cudaGetSymbolAddress((void**)&featB, g_featB);

    dim3 gblk(64, 8);
    const int gemm_grid = (NN + 7) / 8;
    const int emax_grid = (EE + 255) / 256;
    const int eacc_grid = (EE * 16 + 255) / 256;
    const int fin_grid  = (NN * 64 + 255) / 256;

    detect_kernel<<<1, 32>>>(ei);
    convert_idx_kernel<<<emax_grid, 256>>>(ei);

    // layer 0 : in 128 -> 4x16, ELU
    gemm_alpha_kernel<128, 4><<<gemm_grid, gblk>>>(x, W0, as0, ad0);
    edge_max_kernel<4><<<emax_grid, 256>>>();
    edge_accum_kernel<4><<<eacc_grid, 256>>>();
    finalize_kernel<4, true><<<fin_grid, 256>>>(b0, featA);

    // layer 1 : 64 -> 4x16, ELU
    gemm_alpha_kernel<64, 4><<<gemm_grid, gblk>>>(featA, W1, as1, ad1);
    edge_max_kernel<4><<<emax_grid, 256>>>();
    edge_accum_kernel<4><<<eacc_grid, 256>>>();
    finalize_kernel<4, true><<<fin_grid, 256>>>(b1, featB);

    // layer 2 : 64 -> 1x64, no ELU, mean over 1 head == identity
    gemm_alpha_kernel<64, 1><<<gemm_grid, gblk>>>(featB, W2, as2, ad2);
    edge_max_kernel<1><<<emax_grid, 256>>>();
    edge_accum_kernel<1><<<eacc_grid, 256>>>();
    finalize_kernel<1, false><<<fin_grid, 256>>>(b2, out);
}

// round 4
// speedup vs baseline: 1.9190x; 1.9190x over previous
#include <cuda_runtime.h>

#define NN 50000
#define EE 800000
#define NEG 0.2f

// ---------------- scratch (device globals; 16B-aligned for v4 access) -------
__device__ __align__(16) int   g_src[EE];
__device__ __align__(16) int   g_dst[EE];
__device__ __align__(16) float g_h[NN * 64];
__device__ __align__(16) float g_featA[NN * 64];
__device__ __align__(16) float g_featB[NN * 64];
__device__ __align__(16) float g_accum[NN * 64];
__device__ __align__(16) float g_as[NN * 4];
__device__ __align__(16) float g_ad[NN * 4];
__device__ __align__(16) float g_den[NN * 4];
__device__ int g_is64;

// ---------------- helpers ---------------------------------------------------
__device__ __forceinline__ void redAddV4(float* a, float4 v) {
    asm volatile("red.global.add.v4.f32 [%0], {%1,%2,%3,%4};"
                 :: "l"(a), "f"(v.x), "f"(v.y), "f"(v.z), "f"(v.w)
                 : "memory");
}

__device__ __forceinline__ float lrelu(float x) { return x > 0.f ? x : NEG * x; }

// ---------------- kernels ---------------------------------------------------
// If edge_index is int64 (values < 2^31), every odd 32-bit word of the first
// 64 lanes is zero. For int32, those words are random node ids.
__global__ void detect_kernel(const int* __restrict__ ei) {
    if (threadIdx.x == 0) {
        int acc = 0;
        for (int i = 1; i < 128; i += 2) acc |= ei[i];
        g_is64 = (acc == 0) ? 1 : 0;
    }
}

__global__ void convert_idx_kernel(const int* __restrict__ ei) {
    int e = blockIdx.x * blockDim.x + threadIdx.x;
    if (e >= EE) return;
    if (g_is64) {
        g_src[e] = ei[2 * e];
        g_dst[e] = ei[2 * (EE + e)];
    } else {
        g_src[e] = ei[e];
        g_dst[e] = ei[EE + e];
    }
}

// h = X @ W ; alpha_s / alpha_d ; zero accum & den.
// 256 threads, 64-node tile, each thread owns a 4x4 register block.
// dynamic smem: sW[FIN][64] then sX[64][FIN+1]  (sX reused for h afterwards)
template <int FIN, int H>
__global__ void gemm_alpha_kernel(const float* __restrict__ X,
                                  const float* __restrict__ W,
                                  const float* __restrict__ As,
                                  const float* __restrict__ Ad) {
    extern __shared__ float smem[];
    float* sW = smem;               // FIN*64
    float* sX = smem + FIN * 64;    // 64*(FIN+1), padded rows

    const int tid = threadIdx.x;
    const int node0 = blockIdx.x * 64;

    // load W (row-major [FIN][64]) via float4
    for (int i = tid; i < FIN * 16; i += 256) {
        float4 v = ((const float4*)W)[i];
        *(float4*)&sW[i * 4] = v;
    }
    // load X tile, scatter scalars into padded rows
    const int KV4 = FIN / 4;
    for (int i = tid; i < 64 * KV4; i += 256) {
        int r = i / KV4, c = i % KV4;
        int node = node0 + r;
        float4 v = (node < NN) ? ((const float4*)(X + (size_t)node * FIN))[c]
                               : make_float4(0.f, 0.f, 0.f, 0.f);
        float* row = &sX[r * (FIN + 1)];
        row[c * 4 + 0] = v.x; row[c * 4 + 1] = v.y;
        row[c * 4 + 2] = v.z; row[c * 4 + 3] = v.w;
    }
    __syncthreads();

    const int tx = tid & 15;   // 4 cols each
    const int ty = tid >> 4;   // 4 nodes each
    float acc[4][4];
#pragma unroll
    for (int i = 0; i < 4; i++)
#pragma unroll
        for (int j = 0; j < 4; j++) acc[i][j] = 0.f;

#pragma unroll 8
    for (int k = 0; k < FIN; k++) {
        float4 w4 = *(const float4*)&sW[k * 64 + tx * 4];
#pragma unroll
        for (int i = 0; i < 4; i++) {
            float xv = sX[(ty * 4 + i) * (FIN + 1) + k];
            acc[i][0] += xv * w4.x;
            acc[i][1] += xv * w4.y;
            acc[i][2] += xv * w4.z;
            acc[i][3] += xv * w4.w;
        }
    }
    __syncthreads();

    // write h, zero accum, stash h into sX region (reused as sH)
#pragma unroll
    for (int i = 0; i < 4; i++) {
        int node = node0 + ty * 4 + i;
        if (node < NN) {
            *(float4*)&g_h[node * 64 + tx * 4] =
                make_float4(acc[i][0], acc[i][1], acc[i][2], acc[i][3]);
            *(float4*)&g_accum[node * 64 + tx * 4] = make_float4(0.f, 0.f, 0.f, 0.f);
        }
        float* row = &sX[(ty * 4 + i) * (FIN + 1) + tx * 4];
        row[0] = acc[i][0]; row[1] = acc[i][1];
        row[2] = acc[i][2]; row[3] = acc[i][3];
    }
    __syncthreads();

    if (H == 4) {
        int local = tid >> 2, head = tid & 3;
        int node = node0 + local;
        const float* hrow = &sX[local * (FIN + 1) + head * 16];
        float s = 0.f, d = 0.f;
#pragma unroll
        for (int f = 0; f < 16; f++) {
            float hv = hrow[f];
            s += hv * As[head * 16 + f];
            d += hv * Ad[head * 16 + f];
        }
        if (node < NN) {
            g_as[node * 4 + head]  = s;
            g_ad[node * 4 + head]  = d;
            g_den[node * 4 + head] = 0.f;
        }
    } else {
        int local = tid >> 2, q = tid & 3;   // 4 threads per node, 16 feats each
        int node = node0 + local;
        const float* hrow = &sX[local * (FIN + 1) + q * 16];
        float s = 0.f, d = 0.f;
#pragma unroll
        for (int f = 0; f < 16; f++) {
            float hv = hrow[f];
            s += hv * As[q * 16 + f];
            d += hv * Ad[q * 16 + f];
        }
        s += __shfl_xor_sync(0xFFFFFFFFu, s, 1);
        s += __shfl_xor_sync(0xFFFFFFFFu, s, 2);
        d += __shfl_xor_sync(0xFFFFFFFFu, d, 1);
        d += __shfl_xor_sync(0xFFFFFFFFu, d, 2);
        if (q == 0 && node < NN) {
            g_as[node]  = s;
            g_ad[node]  = d;
            g_den[node] = 0.f;
        }
    }
}

// 16 threads per edge; each handles 4 contiguous feature columns.
// Unshifted softmax: w = exp(lrelu(as[s]+ad[d])), accumulated un-normalized.
template <int H>
__global__ void edge_accum_kernel() {
    int idx = blockIdx.x * blockDim.x + threadIdx.x;   // grid sized exactly
    int e = idx >> 4;
    int j = idx & 15;
    int lane = threadIdx.x & 31;
    int s = g_src[e], d = g_dst[e];

    float w;
    if (H == 4) {
        int head = j >> 2;
        w = __expf(lrelu(g_as[s * 4 + head] + g_ad[d * 4 + head]));
    } else {
        w = __expf(lrelu(g_as[s] + g_ad[d]));
    }

    float4 hv = *(const float4*)&g_h[s * 64 + j * 4];
    redAddV4(&g_accum[d * 64 + j * 4],
             make_float4(hv.x * w, hv.y * w, hv.z * w, hv.w * w));

    if (H == 4) {
        int base = lane & 16;
        float w0 = __shfl_sync(0xFFFFFFFFu, w, base + 0);
        float w1 = __shfl_sync(0xFFFFFFFFu, w, base + 4);
        float w2 = __shfl_sync(0xFFFFFFFFu, w, base + 8);
        float w3 = __shfl_sync(0xFFFFFFFFu, w, base + 12);
        if (j == 0) redAddV4(&g_den[d * 4], make_float4(w0, w1, w2, w3));
    } else {
        if (j == 0) atomicAdd(&g_den[d], w);
    }
}

template <int H, bool ELU>
__global__ void finalize_kernel(const float* __restrict__ bias,
                                float* __restrict__ out) {
    int idx = blockIdx.x * blockDim.x + threadIdx.x;
    if (idx >= NN * 64) return;
    int node = idx >> 6;
    int col  = idx & 63;
    int head = (H == 4) ? (col >> 4) : 0;
    // self-loop contribution added analytically
    float w   = __expf(lrelu(g_as[node * H + head] + g_ad[node * H + head]));
    float num = g_accum[idx] + w * g_h[idx];
    float den = g_den[node * H + head] + w + 1e-16f;
    float v = num / den + bias[col];
    if (ELU) v = v > 0.f ? v : expm1f(v);
    out[idx] = v;
}

// ---------------- launch -----------------------------------------------------
extern "C" void kernel_launch(void* const* d_in, const int* in_sizes, int n_in,
                              void* d_out, int out_size) {
    const float* x   = (const float*)d_in[0];
    const int*   ei  = (const int*)d_in[1];
    const float* W0  = (const float*)d_in[2];
    const float* as0 = (const float*)d_in[3];
    const float* ad0 = (const float*)d_in[4];
    const float* b0  = (const float*)d_in[5];
    const float* W1  = (const float*)d_in[6];
    const float* as1 = (const float*)d_in[7];
    const float* ad1 = (const float*)d_in[8];
    const float* b1  = (const float*)d_in[9];
    const float* W2  = (const float*)d_in[10];
    const float* as2 = (const float*)d_in[11];
    const float* ad2 = (const float*)d_in[12];
    const float* b2  = (const float*)d_in[13];
    float* out = (float*)d_out;

    float *featA, *featB;
    cudaGetSymbolAddress((void**)&featA, g_featA);
    cudaGetSymbolAddress((void**)&featB, g_featB);

    const int smem128 = (128 * 64 + 64 * 129) * 4;   // 65792 B
    const int smem64  = (64 * 64 + 64 * 65) * 4;     // 33024 B
    cudaFuncSetAttribute(gemm_alpha_kernel<128, 4>,
                         cudaFuncAttributeMaxDynamicSharedMemorySize, smem128);
    cudaFuncSetAttribute(gemm_alpha_kernel<64, 4>,
                         cudaFuncAttributeMaxDynamicSharedMemorySize, smem64);
    cudaFuncSetAttribute(gemm_alpha_kernel<64, 1>,
                         cudaFuncAttributeMaxDynamicSharedMemorySize, smem64);

    const int gemm_grid = (NN + 63) / 64;
    const int conv_grid = (EE + 255) / 256;
    const int eacc_grid = (EE * 16) / 256;            // exact
    const int fin_grid  = (NN * 64 + 255) / 256;

    detect_kernel<<<1, 32>>>(ei);
    convert_idx_kernel<<<conv_grid, 256>>>(ei);

    // layer 0 : 128 -> 4x16, ELU
    gemm_alpha_kernel<128, 4><<<gemm_grid, 256, smem128>>>(x, W0, as0, ad0);
    edge_accum_kernel<4><<<eacc_grid, 256>>>();
    finalize_kernel<4, true><<<fin_grid, 256>>>(b0, featA);

    // layer 1 : 64 -> 4x16, ELU
    gemm_alpha_kernel<64, 4><<<gemm_grid, 256, smem64>>>(featA, W1, as1, ad1);
    edge_accum_kernel<4><<<eacc_grid, 256>>>();
    finalize_kernel<4, true><<<fin_grid, 256>>>(b1, featB);

    // layer 2 : 64 -> 1x64, no ELU
    gemm_alpha_kernel<64, 1><<<gemm_grid, 256, smem64>>>(featB, W2, as2, ad2);
    edge_accum_kernel<1><<<eacc_grid, 256>>>();
    finalize_kernel<1, false><<<fin_grid, 256>>>(b2, out);
}